// round 17
// baseline (speedup 1.0000x reference)
#include <cuda_runtime.h>
#include <cuda_fp16.h>
#include <math.h>

#define BN_ 4
#define CI 256
#define CO 256
#define HN 64
#define WN 64
#define KK 9
#define EPS 1e-5f
#define PAD 40      // offconv rows: 32 data + 8 pad halfs = 80B
#define PAD2 72     // main rows: 64 data + 8 pad halfs = 144B

// ---------------- scratch (device globals; no allocation) ----------------
__device__ __half g_xt[BN_*HN*WN*CI];       // x transposed to [b][y][x][c], fp16
__device__ __half g_woffh[KK*32*CI];        // offset weights fp16 [tap][o(pad32)][c]
__device__ __half g_wth[KK*CO*CI];          // main weights fp16 [tap][o][c]

static __device__ __forceinline__ unsigned smem_u32(const void* p) {
    return (unsigned)__cvta_generic_to_shared(p);
}

static __device__ __forceinline__ void mma_f16(float* c, const unsigned* a, const unsigned* b) {
    asm volatile(
        "mma.sync.aligned.m16n8k16.row.col.f32.f16.f16.f32 "
        "{%0,%1,%2,%3}, {%4,%5,%6,%7}, {%8,%9}, {%0,%1,%2,%3};"
        : "+f"(c[0]), "+f"(c[1]), "+f"(c[2]), "+f"(c[3])
        : "r"(a[0]), "r"(a[1]), "r"(a[2]), "r"(a[3]), "r"(b[0]), "r"(b[1]));
}

static __device__ __forceinline__ void ldmat_x4(unsigned* r, unsigned addr) {
    asm volatile("ldmatrix.sync.aligned.m8n8.x4.shared.b16 {%0,%1,%2,%3}, [%4];"
                 : "=r"(r[0]), "=r"(r[1]), "=r"(r[2]), "=r"(r[3]) : "r"(addr));
}

static __device__ __forceinline__ void cp_async16(unsigned dst, const void* src) {
    asm volatile("cp.async.cg.shared.global [%0], [%1], 16;" :: "r"(dst), "l"(src));
}
static __device__ __forceinline__ void cp_async_commit() {
    asm volatile("cp.async.commit_group;");
}
static __device__ __forceinline__ void cp_async_wait0() {
    asm volatile("cp.async.wait_group 0;" ::: "memory");
}

static __device__ __forceinline__ __half2 u2h2(unsigned u) {
    return *reinterpret_cast<const __half2*>(&u);
}
static __device__ __forceinline__ unsigned h22u(__half2 h) {
    return *reinterpret_cast<const unsigned*>(&h);
}

// ---------------- P: fused transpose + weight re-layout ----------------
#define PREP_TRANSPOSE_BLKS (BN_ * (CI / 32) * (HN * WN / 32))   // 4096

__global__ __launch_bounds__(256) void k_prep(const float* __restrict__ x,
                                              const float* __restrict__ w_off,
                                              const float* __restrict__ weight) {
    int bid = blockIdx.x;
    int tid = threadIdx.x;
    if (bid < PREP_TRANSPOSE_BLKS) {
        __shared__ float tile[32][33];
        int b  = bid >> 10;
        int c0 = ((bid >> 7) & 7) * 32;
        int p0 = (bid & 127) * 32;
        int tx = tid & 31, ty = tid >> 5;
        const float* xb = x + (size_t)b * CI * HN * WN;
        #pragma unroll
        for (int j = 0; j < 32; j += 8)
            tile[ty + j][tx] = xb[(c0 + ty + j) * (HN * WN) + p0 + tx];
        __syncthreads();
        __half* xtb = g_xt + (size_t)b * HN * WN * CI;
        #pragma unroll
        for (int j = 0; j < 32; j += 8)
            xtb[(p0 + ty + j) * CI + c0 + tx] = __float2half_rn(tile[tx][ty + j]);
    } else if (bid < PREP_TRANSPOSE_BLKS + CO) {
        __shared__ float wrow[CI * KK];
        int o = bid - PREP_TRANSPOSE_BLKS;
        const float* src = weight + (size_t)o * CI * KK;
        #pragma unroll
        for (int j = 0; j < KK; j++)
            wrow[tid + 256 * j] = src[tid + 256 * j];
        __syncthreads();
        int c = tid;
        #pragma unroll
        for (int tap = 0; tap < KK; tap++)
            g_wth[((size_t)tap * CO + o) * CI + c] = __float2half_rn(wrow[c * KK + tap]);
    } else {
        __shared__ float wrow[CI * KK];
        int o = bid - PREP_TRANSPOSE_BLKS - CO;
        if (o < 27) {
            const float* src = w_off + (size_t)o * CI * KK;
            #pragma unroll
            for (int j = 0; j < KK; j++)
                wrow[tid + 256 * j] = src[tid + 256 * j];
        } else {
            #pragma unroll
            for (int j = 0; j < KK; j++)
                wrow[tid + 256 * j] = 0.f;
        }
        __syncthreads();
        int c = tid;
        #pragma unroll
        for (int tap = 0; tap < KK; tap++)
            g_woffh[((size_t)tap * 32 + o) * CI + c] = __float2half_rn(wrow[c * KK + tap]);
    }
}

// ---------------- G: fully fused offconv + meta + sample + GEMM + BN + ReLU ------------
#define AS_ELEMS (128 * PAD2)
#define BS_ELEMS (256 * PAD2)
#define STEPS 36   // 9 taps * 4 chunks of 64 ch

// dyn smem layout (bytes)
#define SO_AS   0
#define SO_BS   (2 * AS_ELEMS * 2)                 // 36864
#define SO_SB9  (SO_BS + 2 * BS_ELEMS * 2)         // 110592
#define SO_SW9  (SO_SB9 + KK * 128 * 16)           // 129024
#define SO_SC   (SO_SW9 + KK * 128 * 16)           // 147456
#define KMAIN_SMEM (SO_SC + 2048)                  // 149504
// offconv temporaries alias the As/Bs region (dead at that point):
#define SO_STRIP 0                                  // 4*66*PAD halfs = 21120 B
#define SO_WOF   22528                              // 9*32*PAD halfs = 23040 B
#define SO_SOM   46080                              // 128*32 floats  = 16384 B

static __device__ __forceinline__ uint4 blend8(const uint4& r0, const uint4& r1,
                                               const uint4& r2, const uint4& r3,
                                               __half2 w0, __half2 w1, __half2 w2, __half2 w3) {
    uint4 o;
    #pragma unroll
    for (int p = 0; p < 4; p++) {
        __half2 a = __hmul2(w0, u2h2((&r0.x)[p]));
        a = __hfma2(w1, u2h2((&r1.x)[p]), a);
        a = __hfma2(w2, u2h2((&r2.x)[p]), a);
        a = __hfma2(w3, u2h2((&r3.x)[p]), a);
        (&o.x)[p] = h22u(a);
    }
    return o;
}

__global__ __launch_bounds__(512, 1) void k_main(const float* __restrict__ b_off,
                                              const float* __restrict__ bias,
                                              const float* __restrict__ gamma,
                                              const float* __restrict__ beta,
                                              const float* __restrict__ rmean,
                                              const float* __restrict__ rvar,
                                              float* __restrict__ out) {
    extern __shared__ __align__(16) char dyn[];
    __half* As    = (__half*)(dyn + SO_AS);               // [2][AS_ELEMS]
    __half* Bs    = (__half*)(dyn + SO_BS);               // [2][BS_ELEMS]
    int4*   SB9   = (int4*)(dyn + SO_SB9);                // [9][128]
    float4* SW9   = (float4*)(dyn + SO_SW9);              // [9][128]
    float*  s_scale = (float*)(dyn + SO_SC);              // [256]
    float*  s_shift = s_scale + 256;                      // [256]

    int m_base = blockIdx.x * 128;
    int tid = threadIdx.x;
    int lane = tid & 31;
    int wid = tid >> 5;
    int wm = wid & 3;          // main: m-warp 0..3 (32 rows)
    int wn = wid >> 2;         // main: n-warp 0..3 (64 cols)

    if (tid < 256) {
        float inv = gamma[tid] * rsqrtf(rvar[tid] + EPS);
        s_scale[tid] = inv;
        s_shift[tid] = beta[tid] - rmean[tid] * inv + bias[tid] * inv;
    }

    unsigned a_row = (unsigned)(lane & 15);
    unsigned a_koff = (unsigned)((lane >> 4) * 8);
    unsigned as_base = smem_u32(As);
    unsigned bs_base = smem_u32(Bs);
    unsigned b_lane_off;   // PAD2 B-frag lane offset (main)
    unsigned b_lane_off40; // PAD B-frag lane offset (offconv)
    {
        int t = lane >> 3, r = lane & 7;
        b_lane_off   = (unsigned)(((t >> 1) * 8 + r) * (PAD2 * 2) + (t & 1) * 16);
        b_lane_off40 = (unsigned)(((t >> 1) * 8 + r) * (PAD * 2) + (t & 1) * 16);
    }

    // ================= PHASE 1: offset conv for this block's 2 rows =================
    {
        __half* strip = (__half*)(dyn + SO_STRIP);   // [4*66][PAD]
        __half* wof   = (__half*)(dyn + SO_WOF);     // [9*32][PAD]
        float*  som   = (float*)(dyn + SO_SOM);      // [128][32]
        unsigned strip_b = smem_u32(strip);
        unsigned wof_b   = smem_u32(wof);

        int b  = m_base >> 12;
        int h0 = (m_base >> 6) & 63;                 // even; block covers h0, h0+1
        const __half* xb = g_xt + (size_t)(b * HN) * WN * CI;

        int wm2 = wid & 7;      // 8 m-tiles of 16
        int wn2 = wid >> 3;     // 2 n-tiles of 16
        int r2 = wm2 >> 2;      // which h row (0/1)
        int w0 = (wm2 * 16) & 63;

        float acc2[2][4];
        #pragma unroll
        for (int i = 0; i < 2; i++)
            #pragma unroll
            for (int j = 0; j < 4; j++) acc2[i][j] = 0.f;

        for (int c0 = 0; c0 < CI; c0 += 32) {
            __syncthreads();
            // strip: 4 y-rows x 66 w x 8 quads of 4ch = 2112 tasks
            for (int idx = tid; idx < 4 * 66 * 8; idx += 512) {
                int y_i = idx / (66 * 8);
                int rest = idx - y_i * (66 * 8);
                int wi = rest >> 3;
                int q = rest & 7;
                int y = h0 + y_i - 1;
                int w = wi - 1;
                uint2 p = make_uint2(0u, 0u);
                if (y >= 0 && y < HN && w >= 0 && w < WN)
                    p = *(const uint2*)&xb[((size_t)y * WN + w) * CI + c0 + q * 4];
                *(uint2*)&strip[(y_i * 66 + wi) * PAD + q * 4] = p;
            }
            // offset weights: 9 taps x 32n x 4 parts = 1152 uint4 tasks
            for (int idx = tid; idx < KK * 128; idx += 512) {
                int tap = idx >> 7;
                int rr = idx & 127;
                int n = rr >> 2, part = rr & 3;
                uint4 v = *(const uint4*)&g_woffh[((size_t)(tap * 32 + n)) * CI + c0 + part * 8];
                *(uint4*)&wof[(tap * 32 + n) * PAD + part * 8] = v;
            }
            __syncthreads();
            #pragma unroll
            for (int tap = 0; tap < KK; tap++) {
                int ky = tap / 3 - 1, kx = tap % 3 - 1;
                unsigned arow0 = (unsigned)((r2 + ky + 1) * 66 + kx + 1 + w0);
                #pragma unroll
                for (int ks = 0; ks < 2; ks++) {
                    unsigned a[4];
                    ldmat_x4(a, strip_b + ((arow0 + a_row) * PAD + ks * 16 + a_koff) * 2);
                    unsigned bb4[4];
                    ldmat_x4(bb4, wof_b + (unsigned)((tap * 32 + wn2 * 16) * (PAD * 2))
                                   + (unsigned)(ks * 32) + b_lane_off40);
                    mma_f16(acc2[0], a, bb4);
                    mma_f16(acc2[1], a, bb4 + 2);
                }
            }
        }
        __syncthreads();
        // stage offconv outputs
        {
            int g = lane >> 2;
            int cq = (lane & 3) * 2;
            #pragma unroll
            for (int nf = 0; nf < 2; nf++) {
                #pragma unroll
                for (int half = 0; half < 2; half++) {
                    int m = wm2 * 16 + half * 8 + g;
                    #pragma unroll
                    for (int j = 0; j < 2; j++) {
                        int n = wn2 * 16 + nf * 8 + cq + j;
                        som[m * 32 + n] = acc2[nf][half * 2 + j];
                    }
                }
            }
        }
        __syncthreads();
        // meta: 128 positions x 9 taps -> SB9/SW9 (smem-local)
        for (int idx = tid; idx < 128 * KK; idx += 512) {
            int k = idx % KK;
            int m = idx / KK;
            int h = h0 + (m >> 6);
            int w = m & 63;
            float dy = som[m * 32 + k]      + b_off[k];
            float dx = som[m * 32 + 9 + k]  + b_off[9 + k];
            float mm = som[m * 32 + 18 + k] + b_off[18 + k];
            float mask = 1.f / (1.f + expf(-mm));
            float py = (float)h + (float)(k / 3 - 1) + dy;
            float px = (float)w + (float)(k % 3 - 1) + dx;
            float y0f = floorf(py), x0f = floorf(px);
            float ly = py - y0f, lx = px - x0f;
            int y0 = (int)y0f, x0 = (int)x0f;
            int y1 = y0 + 1, x1 = x0 + 1;
            float vy0 = (y0 >= 0 && y0 < HN) ? 1.f : 0.f;
            float vy1 = (y1 >= 0 && y1 < HN) ? 1.f : 0.f;
            float vx0 = (x0 >= 0 && x0 < WN) ? 1.f : 0.f;
            float vx1 = (x1 >= 0 && x1 < WN) ? 1.f : 0.f;
            int yc0 = min(max(y0, 0), HN - 1), yc1 = min(max(y1, 0), HN - 1);
            int xc0 = min(max(x0, 0), WN - 1), xc1 = min(max(x1, 0), WN - 1);
            float4 wv;
            wv.x = (1.f - ly) * (1.f - lx) * mask * vy0 * vx0;
            wv.y = (1.f - ly) * lx         * mask * vy0 * vx1;
            wv.z = ly * (1.f - lx)         * mask * vy1 * vx0;
            wv.w = ly * lx                 * mask * vy1 * vx1;
            int bb = b * HN * WN;
            int4 bv;
            bv.x = (bb + yc0 * WN + xc0) * CI;
            bv.y = (bb + yc0 * WN + xc1) * CI;
            bv.z = (bb + yc1 * WN + xc0) * CI;
            bv.w = (bb + yc1 * WN + xc1) * CI;
            SB9[k * 128 + m] = bv;
            SW9[k * 128 + m] = wv;
        }
        __syncthreads();
    }

    // ================= PHASE 2: main GEMM =================
    float acc[2][8][4];
    #pragma unroll
    for (int i = 0; i < 2; i++)
        #pragma unroll
        for (int j = 0; j < 8; j++)
            #pragma unroll
            for (int q = 0; q < 4; q++) acc[i][j][q] = 0.f;

    const int tk_m[2]   = { tid >> 3, (tid + 512) >> 3 };
    const int tk_oct[2] = { tid & 7,  tid & 7 };
    const int as_off[2] = { tk_m[0] * PAD2 + tk_oct[0] * 8,
                            tk_m[1] * PAD2 + tk_oct[1] * 8 };

    // ---- build step 0 into buffer 0 (blocking) ----
    {
        #pragma unroll
        for (int t = 0; t < 2; t++) {
            int4 bs = SB9[tk_m[t]];
            float4 wf = SW9[tk_m[t]];
            int c = tk_oct[t] * 8;
            uint4 r0 = *(const uint4*)&g_xt[bs.x + c];
            uint4 r1 = *(const uint4*)&g_xt[bs.y + c];
            uint4 r2 = *(const uint4*)&g_xt[bs.z + c];
            uint4 r3 = *(const uint4*)&g_xt[bs.w + c];
            __half2 w0 = __float2half2_rn(wf.x), w1 = __float2half2_rn(wf.y);
            __half2 w2 = __float2half2_rn(wf.z), w3 = __float2half2_rn(wf.w);
            *(uint4*)&As[as_off[t]] = blend8(r0, r1, r2, r3, w0, w1, w2, w3);
        }
        #pragma unroll
        for (int j = 0; j < 4; j++) {
            int idx = tid + 512 * j;          // 0..2047
            int n = idx >> 3;
            int part = idx & 7;
            uint4 v = *(const uint4*)&g_wth[(size_t)n * CI + part * 8];
            *(uint4*)&Bs[n * PAD2 + part * 8] = v;
        }
    }
    __syncthreads();

    for (int s = 0; s < STEPS; s++) {
        int cur = s & 1, nxt = cur ^ 1;

        bool have_next = (s + 1 < STEPS);
        int tap1 = (s + 1) >> 2;
        int c01 = ((s + 1) & 3) * 64;
        const int4*   SBt = SB9 + tap1 * 128;
        const float4* SWt = SW9 + tap1 * 128;
        unsigned ab = as_base + cur * (AS_ELEMS * 2);
        unsigned bb_base = bs_base + cur * (BS_ELEMS * 2) + (unsigned)(wn * 64) * (PAD2 * 2) + b_lane_off;

        // ---- cp.async B(s+1) ----
        if (have_next) {
            const __half* wb = g_wth + (size_t)tap1 * CO * CI + c01;
            unsigned bdst = bs_base + (unsigned)(nxt * BS_ELEMS * 2);
            #pragma unroll
            for (int j = 0; j < 4; j++) {
                int idx = tid + 512 * j;
                int n = idx >> 3;
                int part = idx & 7;
                cp_async16(bdst + (unsigned)(n * PAD2 + part * 8) * 2, &wb[(size_t)n * CI + part * 8]);
            }
            cp_async_commit();
        }

        // ---- gather task0 LDGs ----
        uint4 r0, r1, r2, r3;
        float4 wf;
        if (have_next) {
            int4 bs = SBt[tk_m[0]];
            wf = SWt[tk_m[0]];
            int c = c01 + tk_oct[0] * 8;
            r0 = *(const uint4*)&g_xt[bs.x + c];
            r1 = *(const uint4*)&g_xt[bs.y + c];
            r2 = *(const uint4*)&g_xt[bs.z + c];
            r3 = *(const uint4*)&g_xt[bs.w + c];
        }

        // ---- mma ks 0,1 ----
        #pragma unroll
        for (int ks = 0; ks < 2; ks++) {
            unsigned a[2][4];
            #pragma unroll
            for (int mf = 0; mf < 2; mf++) {
                unsigned row = (unsigned)(wm * 32 + mf * 16) + a_row;
                ldmat_x4(a[mf], ab + row * (PAD2 * 2) + (ks * 16 + a_koff) * 2);
            }
            #pragma unroll
            for (int nf2 = 0; nf2 < 4; nf2++) {
                unsigned bb4[4];
                ldmat_x4(bb4, bb_base + (unsigned)(nf2 * 16) * (PAD2 * 2) + (unsigned)(ks * 32));
                #pragma unroll
                for (int mf = 0; mf < 2; mf++) {
                    mma_f16(acc[mf][nf2 * 2],     a[mf], bb4);
                    mma_f16(acc[mf][nf2 * 2 + 1], a[mf], bb4 + 2);
                }
            }
        }

        // ---- blend+STS task0; gather task1 ----
        if (have_next) {
            __half2 w0 = __float2half2_rn(wf.x), w1 = __float2half2_rn(wf.y);
            __half2 w2 = __float2half2_rn(wf.z), w3 = __float2half2_rn(wf.w);
            *(uint4*)&As[nxt * AS_ELEMS + as_off[0]] = blend8(r0, r1, r2, r3, w0, w1, w2, w3);
            int4 bs = SBt[tk_m[1]];
            wf = SWt[tk_m[1]];
            int c = c01 + tk_oct[1] * 8;
            r0 = *(const uint4*)&g_xt[bs.x + c];
            r1 = *(const uint4*)&g_xt[bs.y + c];
            r2 = *(const uint4*)&g_xt[bs.z + c];
            r3 = *(const uint4*)&g_xt[bs.w + c];
        }

        // ---- mma ks 2,3 ----
        #pragma unroll
        for (int ks = 2; ks < 4; ks++) {
            unsigned a[2][4];
            #pragma unroll
            for (int mf = 0; mf < 2; mf++) {
                unsigned row = (unsigned)(wm * 32 + mf * 16) + a_row;
                ldmat_x4(a[mf], ab + row * (PAD2 * 2) + (ks * 16 + a_koff) * 2);
            }
            #pragma unroll
            for (int nf2 = 0; nf2 < 4; nf2++) {
                unsigned bb4[4];
                ldmat_x4(bb4, bb_base + (unsigned)(nf2 * 16) * (PAD2 * 2) + (unsigned)(ks * 32));
                #pragma unroll
                for (int mf = 0; mf < 2; mf++) {
                    mma_f16(acc[mf][nf2 * 2],     a[mf], bb4);
                    mma_f16(acc[mf][nf2 * 2 + 1], a[mf], bb4 + 2);
                }
            }
        }

        // ---- blend+STS task1; drain cp.async ----
        if (have_next) {
            __half2 w0 = __float2half2_rn(wf.x), w1 = __float2half2_rn(wf.y);
            __half2 w2 = __float2half2_rn(wf.z), w3 = __float2half2_rn(wf.w);
            *(uint4*)&As[nxt * AS_ELEMS + as_off[1]] = blend8(r0, r1, r2, r3, w0, w1, w2, w3);
            cp_async_wait0();
        }
        __syncthreads();
    }

    // ---- epilogue: BN(+bias) + ReLU, write NCHW ----
    int g = lane >> 2;
    int cq = (lane & 3) * 2;
    #pragma unroll
    for (int mf = 0; mf < 2; mf++) {
        int row0 = m_base + wm * 32 + mf * 16 + g;
        #pragma unroll
        for (int half = 0; half < 2; half++) {
            int m = row0 + half * 8;
            int b = m >> 12, h = (m >> 6) & 63, w = m & 63;
            float* orow = out + ((size_t)b * CO * HN + h) * WN + w;
            #pragma unroll
            for (int nf = 0; nf < 8; nf++) {
                int nl0 = wn * 64 + nf * 8 + cq;
                #pragma unroll
                for (int j = 0; j < 2; j++) {
                    int nl = nl0 + j;
                    float v = acc[mf][nf][half * 2 + j] * s_scale[nl] + s_shift[nl];
                    orow[(size_t)nl * HN * WN] = fmaxf(v, 0.f);
                }
            }
        }
    }
}

// ---------------- launch ----------------
extern "C" void kernel_launch(void* const* d_in, const int* in_sizes, int n_in,
                              void* d_out, int out_size) {
    const float* x      = (const float*)d_in[0];
    const float* w_off  = (const float*)d_in[1];
    const float* b_off  = (const float*)d_in[2];
    const float* weight = (const float*)d_in[3];
    const float* bias   = (const float*)d_in[4];
    const float* gamma  = (const float*)d_in[5];
    const float* beta   = (const float*)d_in[6];
    const float* rmean  = (const float*)d_in[7];
    const float* rvar   = (const float*)d_in[8];
    float* out = (float*)d_out;

    static bool attr_done = false;
    if (!attr_done) {
        cudaFuncSetAttribute(k_main, cudaFuncAttributeMaxDynamicSharedMemorySize, KMAIN_SMEM);
        attr_done = true;
    }

    k_prep<<<PREP_TRANSPOSE_BLKS + CO + 32, 256>>>(x, w_off, weight);
    k_main<<<BN_ * HN * WN / 128, 512, KMAIN_SMEM>>>(b_off, bias, gamma, beta, rmean, rvar, out);
}